// round 8
// baseline (speedup 1.0000x reference)
#include <cuda_runtime.h>
#include <cstdint>
#include <math.h>

// ---------------------------------------------------------------------------
// ClassicalMappedQRNN fast path (alpha=beta=pi/2). B=8192 chains, S=4096.
// WARP-SPECIALIZED: block = 128 threads = 4 warps on 4 SMSPs.
//   warps 0,1 : serial recurrence, 32 chains each (1 chain/thread)
//   warps 2,3 : trig producers for warps 0,1 resp. (same chains)
// Producer streams per step a float4 (C, S, c, -) into smem:
//   C = sqrt2*cos(phi/2) = sqrt(1+r),  S = sqrt2*sin(phi/2) = x r/sqrt(1+r),
//   r = rsqrt(1+x^2),  c_t = 2(C_{t-1}C_t + S_{t-1}S_t)      [input-only]
// Serial step (state G, K = sqrt2/||G||, v=(C,-S,S,C), ||v||=2):
//   up = C*gm + S*bt       (gm,bt = butterflies of G_{t-2}; 2-step slack)
//   z  = c - qK2 * up      (= d_t, off-chain; qK2 = 2*K_{t-2})
//   m  = 4 + K_{t-1} z;  K_t = rsqrt(m)     <- serial core: FFMA+RSQ = 20cyc
//   w  = butterflies(G);  G' = K w + v       (8 FMA-class; -S via FFMA negate)
// Parity queues (t&1) avoid any queue-rotation movs.
// Double-buffered 16-step chunks in 32KB STATIC smem + named barriers.
// ---------------------------------------------------------------------------

#define CHUNK  16
#define TPB    128
#define GUARD4 4.000021f

__device__ __forceinline__ float rsqa(float x) {
    float y; asm("rsqrt.approx.f32 %0, %1;" : "=f"(y) : "f"(x)); return y;
}
__device__ __forceinline__ void barp(int id) {
    asm volatile("bar.sync %0, 64;" :: "r"(id) : "memory");
}

// [pair(2)][buf(2)][t(16)][lane(32)] float4 = 32768 bytes (static)
__shared__ float4 sb4[2 * 2 * CHUNK * 32];

// ---------------- serial side ----------------
struct SState {
    float g0, g1, g2, g3, K;
    float qg[2], qb[2], qK2[2];   // from step t-2: butterflies + doubled K
};

__device__ __forceinline__ void s_init(SState& s, float4 f) {
    s.g0 = f.x; s.g1 = -f.y; s.g2 = f.y; s.g3 = f.x;  // G0 = v0 = (C,-S,S,C)
    s.K  = 0.70710678118654752f;                       // sqrt2/||G0||, ||G0||=2
    s.qg[0] = 0.0f; s.qb[0] = 0.0f;                    // butterflies of G0 = 0
    s.qK2[0] = 1.41421356237309505f;
}

__device__ __forceinline__ void s_tail(SState& s, float4 f, float Kn, int par,
                                       float w0, float w1, float w2, float w3) {
    float n0 = fmaf(s.K, w0,  f.x);
    float n1 = fmaf(s.K, w1, -f.y);
    float n2 = fmaf(s.K, w2,  f.y);
    float n3 = fmaf(s.K, w3,  f.x);
    s.qg[par]  = n1 + n2;
    s.qb[par]  = n0 - n3;
    s.qK2[par] = Kn + Kn;
    s.g0 = n0; s.g1 = n1; s.g2 = n2; s.g3 = n3; s.K = Kn;
}

__device__ __forceinline__ void s_direct(SState& s, float4 f, int par) {
    float w0 = s.g0 - s.g1, w1 = s.g0 + s.g1;
    float w2 = s.g2 + s.g3, w3 = s.g3 - s.g2;
    float d  = fmaf(f.y, w2 - w1, f.x * (w0 + w3));
    float m  = fmaf(s.K, d, GUARD4);
    float Kn = rsqa(m);
    s_tail(s, f, Kn, par, w0, w1, w2, w3);
}

__device__ __forceinline__ void s_step(SState& s, float4 f, int par) {
    float up = fmaf(f.y, s.qb[par], f.x * s.qg[par]);  // C*gm + S*bt
    float z  = fmaf(-s.qK2[par], up, f.z);             // d_t (off-chain)
    float m  = fmaf(s.K, z, GUARD4);                   // ON CHAIN
    float Kn = rsqa(m);                                // ON CHAIN (20 cyc)
    float w0 = s.g0 - s.g1, w1 = s.g0 + s.g1;
    float w2 = s.g2 + s.g3, w3 = s.g3 - s.g2;
    s_tail(s, f, Kn, par, w0, w1, w2, w3);
}

__device__ __forceinline__ void s_renorm(SState& s) {
    float ss = (s.g0 * s.g0 + s.g1 * s.g1) + (s.g2 * s.g2 + s.g3 * s.g3);
    s.K = rsqa(0.5f * ss);                             // exact sqrt2/||G||
}

template <bool FIRST>
__device__ __forceinline__ void consume_chunk(SState& s, const float4* sb) {
    #pragma unroll
    for (int t = 0; t < CHUNK; t++) {
        float4 f = sb[t * 32];
        if (FIRST && t == 0)      s_init(s, f);
        else if (FIRST && t == 1) s_direct(s, f, 1);
        else                      s_step(s, f, t & 1);
    }
    s_renorm(s);   // kills approx-rsqrt drift every 16 steps
}

// ---------------- producer side ----------------
struct PReg { float4 a[CHUNK / 4]; };

__device__ __forceinline__ void p_load(PReg& r, const float* __restrict__ xrow,
                                       int c) {
    const float4* p = reinterpret_cast<const float4*>(xrow + c * CHUNK);
    #pragma unroll
    for (int i = 0; i < CHUNK / 4; i++) r.a[i] = __ldg(p + i);
}

__device__ __forceinline__ void p_emit(float x, float& Cp, float& Sp,
                                       float4* dst) {
    float tq = fmaf(x, x, 1.0f);
    float r  = rsqa(tq);
    float e  = r + 1.0f;
    float q  = rsqa(e);
    float C  = e * q;                      // sqrt2 cos(phi/2)
    float S  = (x * r) * q;                // sqrt2 sin(phi/2)
    float cc = fmaf(S, Sp, C * Cp);
    float c2 = cc + cc;                    // 2(CC'+SS')
    *dst = make_float4(C, S, c2, 0.0f);
    Cp = C; Sp = S;
}

__device__ __forceinline__ void p_chunk(const PReg& r, float& Cp, float& Sp,
                                        float4* wb) {
    #pragma unroll
    for (int i = 0; i < CHUNK / 4; i++) {
        p_emit(r.a[i].x, Cp, Sp, wb + (i * 4 + 0) * 32);
        p_emit(r.a[i].y, Cp, Sp, wb + (i * 4 + 1) * 32);
        p_emit(r.a[i].z, Cp, Sp, wb + (i * 4 + 2) * 32);
        p_emit(r.a[i].w, Cp, Sp, wb + (i * 4 + 3) * 32);
    }
}

// ---------------- fallback ----------------
__device__ void run_simple(const float* __restrict__ xrow, float* __restrict__ outb,
                           int S, float ca, float sa, float cb, float sb) {
    float h0 = 0.f, h1 = 0.f, h2 = 0.f, h3 = 0.f;
    for (int t = 0; t < S; t++) {
        float xv = xrow[t];
        float phi = atanf(xv);
        float c = cosf(0.5f * phi);
        float s = sinf(0.5f * phi);
        float u0 = ca * c + cb * h0 - sb * h1;
        float u1 = -(sa * s) + sb * h0 + cb * h1;
        float u2 = ca * s + cb * h2 + sb * h3;
        float u3 = sa * c - sb * h2 + cb * h3;
        float ss = u0*u0 + u1*u1 + u2*u2 + u3*u3;
        float rn = rsqrtf(ss);
        h0 = u0 * rn; h1 = u1 * rn; h2 = u2 * rn; h3 = u3 * rn;
    }
    *outb = (h0*h0 + h1*h1) - (h2*h2 + h3*h3);
}

// ---------------- kernel ----------------
__global__ void __launch_bounds__(TPB, 1)
qrnn_kernel(const float* __restrict__ x, const float* __restrict__ pa,
            const float* __restrict__ pb, float* __restrict__ out, int B, int S) {
    int tid  = threadIdx.x;
    int wid  = tid >> 5;
    int lane = tid & 31;

    float alpha = __ldg(pa);
    float beta  = __ldg(pb);
    const float PIO2 = 1.57079632679489662f;
    bool fast = (fabsf(alpha - PIO2) < 1e-5f) && (fabsf(beta - PIO2) < 1e-5f)
                && (S % 64 == 0) && (S >= 128);

    if (!fast) {
        if (tid < 64) {
            int b = blockIdx.x * 64 + tid;
            if (b < B) {
                float ca = cosf(0.5f * alpha), sa = sinf(0.5f * alpha);
                float cb = cosf(0.5f * beta),  sb = sinf(0.5f * beta);
                run_simple(x + (size_t)b * S, out + b, S, ca, sa, cb, sb);
            }
        }
        return;
    }

    const int nch = S / CHUNK;        // multiple of 4 (S % 64 == 0)

    if (wid < 2) {
        // ------------- serial role -------------
        int w  = wid;
        int b  = blockIdx.x * 64 + w * 32 + lane;
        int id = 1 + w;
        const float4* rb0 = sb4 + (w * 2 + 0) * (CHUNK * 32) + lane;
        const float4* rb1 = sb4 + (w * 2 + 1) * (CHUNK * 32) + lane;

        SState s;
        barp(id);                                  // wait: chunk 0 ready
        #pragma unroll 1
        for (int c = 0; c < nch; c++) {
            if (c == 0) consume_chunk<true >(s, rb0);
            else        consume_chunk<false>(s, (c & 1) ? rb1 : rb0);
            barp(id);
        }

        if (b < B) {
            float a01 = s.g0 * s.g0 + s.g1 * s.g1;
            float a23 = s.g2 * s.g2 + s.g3 * s.g3;
            out[b] = (a01 - a23) / (a01 + a23);
        }
    } else {
        // ------------- producer role -------------
        int w  = wid - 2;
        int b  = blockIdx.x * 64 + w * 32 + lane;
        if (b >= B) b = B - 1;                     // clamp (keeps bars uniform)
        int id = 1 + w;
        const float* xrow = x + (size_t)b * S;
        float4* wb0 = sb4 + (w * 2 + 0) * (CHUNK * 32) + lane;
        float4* wb1 = sb4 + (w * 2 + 1) * (CHUNK * 32) + lane;

        float Cp = 0.0f, Sp = 0.0f;
        PReg ra, rbuf;
        p_load(ra, xrow, 0);

        #pragma unroll 1
        for (int c = 0; c < nch; c += 2) {
            int c1 = (c + 1 < nch) ? c + 1 : c;
            p_load(rbuf, xrow, c1);
            p_chunk(ra, Cp, Sp, wb0);              // chunk c   -> buf 0
            barp(id);
            int c2 = (c + 2 < nch) ? c + 2 : c1;
            p_load(ra, xrow, c2);
            p_chunk(rbuf, Cp, Sp, wb1);            // chunk c+1 -> buf 1
            barp(id);
        }
        barp(id);                                  // match serial's final wait
    }
}

extern "C" void kernel_launch(void* const* d_in, const int* in_sizes, int n_in,
                              void* d_out, int out_size) {
    const float* x  = (const float*)d_in[0];
    const float* pa = (const float*)d_in[1];
    const float* pb = (const float*)d_in[2];
    float* out = (float*)d_out;

    int B = out_size;                 // 8192
    int S = in_sizes[0] / B;          // 4096

    int grid = (B + 63) / 64;         // 128 blocks x 128 threads, 1 block/SM
    qrnn_kernel<<<grid, TPB>>>(x, pa, pb, out, B, S);
}

// round 10
// speedup vs baseline: 1.0057x; 1.0057x over previous
#include <cuda_runtime.h>
#include <cstdint>
#include <math.h>

// ---------------------------------------------------------------------------
// ClassicalMappedQRNN fast path (alpha=beta=pi/2). B=8192 chains, S=4096.
// WARP-SPECIALIZED: block = 128 threads = 4 warps on 4 SMSPs.
//   warps 0,1 : serial recurrence, 32 chains each (1 chain/thread)
//   warps 2,3 : trig producers for warps 0,1 resp. (same chains)
// Producer streams per step a float4 (C, S, c, -) into smem:
//   C = sqrt2*cos(phi/2) = sqrt(1+r),  S = sqrt2*sin(phi/2) = x r/sqrt(1+r),
//   r = rsqrt(1+x^2),  c_t = 2(C_{t-1}C_t + S_{t-1}S_t)      [input-only]
// Serial step (state G, K = sqrt2/||G||, v=(C,-S,S,C), ||v||=2):
//   up = C*gm + S*bt       (gm,bt = butterflies of G_{t-2}; 2-step slack)
//   z  = c - qK2 * up      (= d_t, off-chain; qK2 = 2*K_{t-2})
//   m  = 4 + K_{t-1} z;  K_t = rsqrt(m)     <- serial core: FFMA+RSQ = 20cyc
//   w  = butterflies(G);  G' = K w + v       (8 FMA-class; -S via FFMA negate)
// Parity queues (t&1) avoid queue-rotation movs.
// R9 fix vs R8: explicit one-step LDS.128 lookahead in the consumer loop —
// the 29-cyc shared-load latency was fully exposed per step (the R8 stall).
// ---------------------------------------------------------------------------

#define CHUNK  16
#define TPB    128
#define GUARD4 4.000021f

__device__ __forceinline__ float rsqa(float x) {
    float y; asm("rsqrt.approx.f32 %0, %1;" : "=f"(y) : "f"(x)); return y;
}
__device__ __forceinline__ void barp(int id) {
    asm volatile("bar.sync %0, 64;" :: "r"(id) : "memory");
}

// [pair(2)][buf(2)][t(16)][lane(32)] float4 = 32768 bytes (static)
__shared__ float4 sb4[2 * 2 * CHUNK * 32];

// ---------------- serial side ----------------
struct SState {
    float g0, g1, g2, g3, K;
    float qg[2], qb[2], qK2[2];   // from step t-2: butterflies + doubled K
};

__device__ __forceinline__ void s_init(SState& s, float4 f) {
    s.g0 = f.x; s.g1 = -f.y; s.g2 = f.y; s.g3 = f.x;  // G0 = v0 = (C,-S,S,C)
    s.K  = 0.70710678118654752f;                       // sqrt2/||G0||, ||G0||=2
    s.qg[0] = 0.0f; s.qb[0] = 0.0f;                    // butterflies of G0 = 0
    s.qK2[0] = 1.41421356237309505f;
}

__device__ __forceinline__ void s_tail(SState& s, float4 f, float Kn, int par,
                                       float w0, float w1, float w2, float w3) {
    float n0 = fmaf(s.K, w0,  f.x);
    float n1 = fmaf(s.K, w1, -f.y);
    float n2 = fmaf(s.K, w2,  f.y);
    float n3 = fmaf(s.K, w3,  f.x);
    s.qg[par]  = n1 + n2;
    s.qb[par]  = n0 - n3;
    s.qK2[par] = Kn + Kn;
    s.g0 = n0; s.g1 = n1; s.g2 = n2; s.g3 = n3; s.K = Kn;
}

__device__ __forceinline__ void s_direct(SState& s, float4 f, int par) {
    float w0 = s.g0 - s.g1, w1 = s.g0 + s.g1;
    float w2 = s.g2 + s.g3, w3 = s.g3 - s.g2;
    float d  = fmaf(f.y, w2 - w1, f.x * (w0 + w3));
    float m  = fmaf(s.K, d, GUARD4);
    float Kn = rsqa(m);
    s_tail(s, f, Kn, par, w0, w1, w2, w3);
}

__device__ __forceinline__ void s_step(SState& s, float4 f, int par) {
    float up = fmaf(f.y, s.qb[par], f.x * s.qg[par]);  // C*gm + S*bt
    float z  = fmaf(-s.qK2[par], up, f.z);             // d_t (off-chain)
    float m  = fmaf(s.K, z, GUARD4);                   // ON CHAIN
    float Kn = rsqa(m);                                // ON CHAIN (20 cyc)
    float w0 = s.g0 - s.g1, w1 = s.g0 + s.g1;
    float w2 = s.g2 + s.g3, w3 = s.g3 - s.g2;
    s_tail(s, f, Kn, par, w0, w1, w2, w3);
}

__device__ __forceinline__ void s_renorm(SState& s) {
    float ss = (s.g0 * s.g0 + s.g1 * s.g1) + (s.g2 * s.g2 + s.g3 * s.g3);
    s.K = rsqa(0.5f * ss);                             // exact sqrt2/||G||
}

// One-step register lookahead — the LDS for step t+1 issues before step t's
// math, hiding the 29-cyc shared-load latency under the ~30-cyc step.
template <bool FIRST>
__device__ __forceinline__ void consume_chunk(SState& s, const float4* sb) {
    float4 f = sb[0];
    #pragma unroll
    for (int t = 0; t < CHUNK; t++) {
        int tn = (t + 1 < CHUNK) ? (t + 1) : t;
        float4 fn = sb[tn * 32];
        if (FIRST && t == 0)      s_init(s, f);
        else if (FIRST && t == 1) s_direct(s, f, 1);
        else                      s_step(s, f, t & 1);
        f = fn;
    }
    s_renorm(s);   // kills approx-rsqrt drift every 16 steps
}

// ---------------- producer side ----------------
struct PReg { float4 a[CHUNK / 4]; };

__device__ __forceinline__ void p_load(PReg& r, const float* __restrict__ xrow,
                                       int c) {
    const float4* p = reinterpret_cast<const float4*>(xrow + c * CHUNK);
    #pragma unroll
    for (int i = 0; i < CHUNK / 4; i++) r.a[i] = __ldg(p + i);
}

__device__ __forceinline__ void p_emit(float x, float& Cp, float& Sp,
                                       float4* dst) {
    float tq = fmaf(x, x, 1.0f);
    float r  = rsqa(tq);
    float e  = r + 1.0f;
    float q  = rsqa(e);
    float C  = e * q;                      // sqrt2 cos(phi/2)
    float S  = (x * r) * q;                // sqrt2 sin(phi/2)
    float cc = fmaf(S, Sp, C * Cp);
    float c2 = cc + cc;                    // 2(CC'+SS')
    *dst = make_float4(C, S, c2, 0.0f);
    Cp = C; Sp = S;
}

__device__ __forceinline__ void p_chunk(const PReg& r, float& Cp, float& Sp,
                                        float4* wb) {
    #pragma unroll
    for (int i = 0; i < CHUNK / 4; i++) {
        p_emit(r.a[i].x, Cp, Sp, wb + (i * 4 + 0) * 32);
        p_emit(r.a[i].y, Cp, Sp, wb + (i * 4 + 1) * 32);
        p_emit(r.a[i].z, Cp, Sp, wb + (i * 4 + 2) * 32);
        p_emit(r.a[i].w, Cp, Sp, wb + (i * 4 + 3) * 32);
    }
}

// ---------------- fallback ----------------
__device__ void run_simple(const float* __restrict__ xrow, float* __restrict__ outb,
                           int S, float ca, float sa, float cb, float sb) {
    float h0 = 0.f, h1 = 0.f, h2 = 0.f, h3 = 0.f;
    for (int t = 0; t < S; t++) {
        float xv = xrow[t];
        float phi = atanf(xv);
        float c = cosf(0.5f * phi);
        float s = sinf(0.5f * phi);
        float u0 = ca * c + cb * h0 - sb * h1;
        float u1 = -(sa * s) + sb * h0 + cb * h1;
        float u2 = ca * s + cb * h2 + sb * h3;
        float u3 = sa * c - sb * h2 + cb * h3;
        float ss = u0*u0 + u1*u1 + u2*u2 + u3*u3;
        float rn = rsqrtf(ss);
        h0 = u0 * rn; h1 = u1 * rn; h2 = u2 * rn; h3 = u3 * rn;
    }
    *outb = (h0*h0 + h1*h1) - (h2*h2 + h3*h3);
}

// ---------------- kernel ----------------
__global__ void __launch_bounds__(TPB, 1)
qrnn_kernel(const float* __restrict__ x, const float* __restrict__ pa,
            const float* __restrict__ pb, float* __restrict__ out, int B, int S) {
    int tid  = threadIdx.x;
    int wid  = tid >> 5;
    int lane = tid & 31;

    float alpha = __ldg(pa);
    float beta  = __ldg(pb);
    const float PIO2 = 1.57079632679489662f;
    bool fast = (fabsf(alpha - PIO2) < 1e-5f) && (fabsf(beta - PIO2) < 1e-5f)
                && (S % 64 == 0) && (S >= 128);

    if (!fast) {
        if (tid < 64) {
            int b = blockIdx.x * 64 + tid;
            if (b < B) {
                float ca = cosf(0.5f * alpha), sa = sinf(0.5f * alpha);
                float cb = cosf(0.5f * beta),  sb = sinf(0.5f * beta);
                run_simple(x + (size_t)b * S, out + b, S, ca, sa, cb, sb);
            }
        }
        return;
    }

    const int nch = S / CHUNK;        // multiple of 4 (S % 64 == 0)

    if (wid < 2) {
        // ------------- serial role -------------
        int w  = wid;
        int b  = blockIdx.x * 64 + w * 32 + lane;
        int id = 1 + w;
        const float4* rb0 = sb4 + (w * 2 + 0) * (CHUNK * 32) + lane;
        const float4* rb1 = sb4 + (w * 2 + 1) * (CHUNK * 32) + lane;

        SState s;
        barp(id);                                  // wait: chunk 0 ready
        #pragma unroll 1
        for (int c = 0; c < nch; c++) {
            if (c == 0) consume_chunk<true >(s, rb0);
            else        consume_chunk<false>(s, (c & 1) ? rb1 : rb0);
            barp(id);
        }

        if (b < B) {
            float a01 = s.g0 * s.g0 + s.g1 * s.g1;
            float a23 = s.g2 * s.g2 + s.g3 * s.g3;
            out[b] = (a01 - a23) / (a01 + a23);
        }
    } else {
        // ------------- producer role -------------
        int w  = wid - 2;
        int b  = blockIdx.x * 64 + w * 32 + lane;
        if (b >= B) b = B - 1;                     // clamp (keeps bars uniform)
        int id = 1 + w;
        const float* xrow = x + (size_t)b * S;
        float4* wb0 = sb4 + (w * 2 + 0) * (CHUNK * 32) + lane;
        float4* wb1 = sb4 + (w * 2 + 1) * (CHUNK * 32) + lane;

        float Cp = 0.0f, Sp = 0.0f;
        PReg ra, rbuf;
        p_load(ra, xrow, 0);

        #pragma unroll 1
        for (int c = 0; c < nch; c += 2) {
            int c1 = (c + 1 < nch) ? c + 1 : c;
            p_load(rbuf, xrow, c1);
            p_chunk(ra, Cp, Sp, wb0);              // chunk c   -> buf 0
            barp(id);
            int c2 = (c + 2 < nch) ? c + 2 : c1;
            p_load(ra, xrow, c2);
            p_chunk(rbuf, Cp, Sp, wb1);            // chunk c+1 -> buf 1
            barp(id);
        }
        barp(id);                                  // match serial's final wait
    }
}

extern "C" void kernel_launch(void* const* d_in, const int* in_sizes, int n_in,
                              void* d_out, int out_size) {
    const float* x  = (const float*)d_in[0];
    const float* pa = (const float*)d_in[1];
    const float* pb = (const float*)d_in[2];
    float* out = (float*)d_out;

    int B = out_size;                 // 8192
    int S = in_sizes[0] / B;          // 4096

    int grid = (B + 63) / 64;         // 128 blocks x 128 threads, 1 block/SM
    qrnn_kernel<<<grid, TPB>>>(x, pa, pb, out, B, S);
}